// round 4
// baseline (speedup 1.0000x reference)
#include <cuda_runtime.h>
#include <math.h>

// Problem constants
#define B_    8
#define S_    1024
#define HID_  1024
#define H_    8
#define HD_   128
#define MD_   8
#define L_    3
#define M_    (B_*S_)      // 8192 rows
#define BH_   (B_*H_)      // 64 batched attention heads
#define EPS_  1e-7f
#define INV_SQRT_D 0.08838834764831845f   // 1/sqrt(128)

// ------------------------------------------------------------------
// Device-global scratch (allocation-free per harness rules)
// ------------------------------------------------------------------
__device__ float g_cur[(size_t)M_ * HID_];          //  32 MB
__device__ float g_qkv[(size_t)M_ * 3 * HID_];      //  96 MB
__device__ float g_Q[(size_t)BH_ * S_ * HD_];       //  32 MB (expmapped)
__device__ float g_Kf[(size_t)BH_ * S_ * HD_];      //  32 MB (expmapped)
__device__ float g_V[(size_t)BH_ * S_ * HD_];       //  32 MB
__device__ float g_P[(size_t)BH_ * S_ * S_];        // 256 MB scores/probs
__device__ float g_O[(size_t)M_ * HID_];            //  32 MB

// ------------------------------------------------------------------
// Copy x -> g_cur (float4 vectorized)
// ------------------------------------------------------------------
__global__ void copy_x_kernel(const float* __restrict__ x) {
    size_t i = (size_t)blockIdx.x * blockDim.x + threadIdx.x;
    ((float4*)g_cur)[i] = ((const float4*)x)[i];
}

// ------------------------------------------------------------------
// Generic SGEMM + bias:  C[M,N] = A[M,K] @ B[K,N] + bias[N]
// 128x128 tile, BK=8, 256 threads, 8x8 microtile.
// Requires M%128==0, N%128==0, K%8==0 (all satisfied here).
// ------------------------------------------------------------------
__global__ __launch_bounds__(256)
void sgemm_bias_kernel(const float* __restrict__ A, const float* __restrict__ Bm,
                       const float* __restrict__ bias, float* __restrict__ C,
                       int M, int N, int K)
{
    __shared__ float As[8][128];
    __shared__ float Bs[8][128];
    const int tid  = threadIdx.x;
    const int brow = blockIdx.y * 128;
    const int bcol = blockIdx.x * 128;
    const int a_r  = tid >> 1;            // 0..127
    const int a_c  = (tid & 1) * 4;       // 0 or 4
    const int b_r  = tid >> 5;            // 0..7
    const int b_c  = (tid & 31) * 4;      // 0..124
    const int tx   = tid & 15;
    const int ty   = tid >> 4;

    float acc[8][8];
    #pragma unroll
    for (int i = 0; i < 8; i++)
        #pragma unroll
        for (int j = 0; j < 8; j++) acc[i][j] = 0.f;

    for (int k0 = 0; k0 < K; k0 += 8) {
        float4 av = *(const float4*)&A[(size_t)(brow + a_r) * K + k0 + a_c];
        As[a_c + 0][a_r] = av.x;
        As[a_c + 1][a_r] = av.y;
        As[a_c + 2][a_r] = av.z;
        As[a_c + 3][a_r] = av.w;
        *(float4*)&Bs[b_r][b_c] = *(const float4*)&Bm[(size_t)(k0 + b_r) * N + bcol + b_c];
        __syncthreads();
        #pragma unroll
        for (int k = 0; k < 8; k++) {
            float ar[8], br[8];
            #pragma unroll
            for (int i = 0; i < 8; i++) ar[i] = As[k][ty * 8 + i];
            #pragma unroll
            for (int j = 0; j < 8; j++) br[j] = Bs[k][tx * 8 + j];
            #pragma unroll
            for (int i = 0; i < 8; i++)
                #pragma unroll
                for (int j = 0; j < 8; j++) acc[i][j] += ar[i] * br[j];
        }
        __syncthreads();
    }

    #pragma unroll
    for (int i = 0; i < 8; i++) {
        int r = brow + ty * 8 + i;
        #pragma unroll
        for (int j = 0; j < 8; j++) {
            int c = bcol + tx * 8 + j;
            C[(size_t)r * N + c] = acc[i][j] + bias[c];
        }
    }
}

// ------------------------------------------------------------------
// Split qkv [B,S,3,H,HD] into Q/K (expmap0 applied) and V,
// laid out as [B*H, S, HD]. One warp = one head vector (128 floats).
// blockIdx.x = b*S+s (8192), blockIdx.y = part (0=q,1=k,2=v), 256 threads.
// ------------------------------------------------------------------
__global__ void split_expmap_kernel() {
    const int bs   = blockIdx.x;
    const int p    = blockIdx.y;
    const int h    = threadIdx.x >> 5;
    const int lane = threadIdx.x & 31;
    const int b = bs >> 10;          // bs / S_
    const int s = bs & 1023;         // bs % S_

    const float4* src = (const float4*)(g_qkv + (size_t)bs * 3 * HID_ + p * HID_ + h * HD_);
    float4 v = src[lane];

    if (p < 2) {
        float ss = v.x * v.x + v.y * v.y + v.z * v.z + v.w * v.w;
        #pragma unroll
        for (int o = 16; o > 0; o >>= 1) ss += __shfl_xor_sync(0xffffffffu, ss, o);
        float n  = fmaxf(sqrtf(ss), EPS_);
        float sc = tanhf(n) / n;
        v.x *= sc; v.y *= sc; v.z *= sc; v.w *= sc;
    }
    float* dst_base = (p == 0) ? g_Q : ((p == 1) ? g_Kf : g_V);
    float4* dst = (float4*)(dst_base + ((size_t)(b * H_ + h) * S_ + s) * HD_);
    dst[lane] = v;
}

// ------------------------------------------------------------------
// Batched scores: P[z] = (Qf[z] @ Kf[z]^T) * inv_sqrt_d
// z = blockIdx.z (64), M=N=1024, K=128. Same 128x128 tiling;
// both operands loaded with the A-pattern (both are [S,HD] row-major).
// ------------------------------------------------------------------
__global__ __launch_bounds__(256)
void scores_kernel() {
    const int z = blockIdx.z;
    const float* A  = g_Q  + (size_t)z * S_ * HD_;
    const float* Km = g_Kf + (size_t)z * S_ * HD_;
    float*       C  = g_P  + (size_t)z * S_ * S_;

    __shared__ float As[8][128];
    __shared__ float Bs[8][128];
    const int tid  = threadIdx.x;
    const int brow = blockIdx.y * 128;
    const int bcol = blockIdx.x * 128;
    const int lr   = tid >> 1;
    const int lc   = (tid & 1) * 4;
    const int tx   = tid & 15;
    const int ty   = tid >> 4;

    float acc[8][8];
    #pragma unroll
    for (int i = 0; i < 8; i++)
        #pragma unroll
        for (int j = 0; j < 8; j++) acc[i][j] = 0.f;

    for (int k0 = 0; k0 < HD_; k0 += 8) {
        float4 av = *(const float4*)&A [(size_t)(brow + lr) * HD_ + k0 + lc];
        As[lc + 0][lr] = av.x; As[lc + 1][lr] = av.y;
        As[lc + 2][lr] = av.z; As[lc + 3][lr] = av.w;
        float4 bv = *(const float4*)&Km[(size_t)(bcol + lr) * HD_ + k0 + lc];
        Bs[lc + 0][lr] = bv.x; Bs[lc + 1][lr] = bv.y;
        Bs[lc + 2][lr] = bv.z; Bs[lc + 3][lr] = bv.w;
        __syncthreads();
        #pragma unroll
        for (int k = 0; k < 8; k++) {
            float ar[8], br[8];
            #pragma unroll
            for (int i = 0; i < 8; i++) ar[i] = As[k][ty * 8 + i];
            #pragma unroll
            for (int j = 0; j < 8; j++) br[j] = Bs[k][tx * 8 + j];
            #pragma unroll
            for (int i = 0; i < 8; i++)
                #pragma unroll
                for (int j = 0; j < 8; j++) acc[i][j] += ar[i] * br[j];
        }
        __syncthreads();
    }

    #pragma unroll
    for (int i = 0; i < 8; i++) {
        int r = brow + ty * 8 + i;
        #pragma unroll
        for (int j = 0; j < 8; j++)
            C[(size_t)r * S_ + bcol + tx * 8 + j] = acc[i][j] * INV_SQRT_D;
    }
}

// ------------------------------------------------------------------
// Row softmax over g_P: 64*1024 rows of 1024. One block per row.
// ------------------------------------------------------------------
__global__ void softmax_kernel() {
    float* row = g_P + (size_t)blockIdx.x * S_;
    const int tid = threadIdx.x;
    float4 v = ((float4*)row)[tid];

    __shared__ float red[256];
    float m = fmaxf(fmaxf(v.x, v.y), fmaxf(v.z, v.w));
    red[tid] = m; __syncthreads();
    for (int s = 128; s > 0; s >>= 1) {
        if (tid < s) red[tid] = fmaxf(red[tid], red[tid + s]);
        __syncthreads();
    }
    m = red[0]; __syncthreads();

    v.x = expf(v.x - m); v.y = expf(v.y - m);
    v.z = expf(v.z - m); v.w = expf(v.w - m);
    float sum = v.x + v.y + v.z + v.w;
    red[tid] = sum; __syncthreads();
    for (int s = 128; s > 0; s >>= 1) {
        if (tid < s) red[tid] += red[tid + s];
        __syncthreads();
    }
    float inv = 1.0f / red[0];
    v.x *= inv; v.y *= inv; v.z *= inv; v.w *= inv;
    ((float4*)row)[tid] = v;
}

// ------------------------------------------------------------------
// Batched PV: O[z] = P[z] @ V[z], M=1024, N=128, K=1024.
// Epilogue scatters directly into [B,S,HID] layout (g_O).
// ------------------------------------------------------------------
__global__ __launch_bounds__(256)
void pv_kernel() {
    const int z = blockIdx.z;
    const int b = z >> 3, h = z & 7;
    const float* A = g_P + (size_t)z * S_ * S_;
    const float* V = g_V + (size_t)z * S_ * HD_;

    __shared__ float As[8][128];
    __shared__ float Bs[8][128];
    const int tid  = threadIdx.x;
    const int brow = blockIdx.y * 128;
    const int a_r  = tid >> 1;
    const int a_c  = (tid & 1) * 4;
    const int b_r  = tid >> 5;
    const int b_c  = (tid & 31) * 4;
    const int tx   = tid & 15;
    const int ty   = tid >> 4;

    float acc[8][8];
    #pragma unroll
    for (int i = 0; i < 8; i++)
        #pragma unroll
        for (int j = 0; j < 8; j++) acc[i][j] = 0.f;

    for (int k0 = 0; k0 < S_; k0 += 8) {
        float4 av = *(const float4*)&A[(size_t)(brow + a_r) * S_ + k0 + a_c];
        As[a_c + 0][a_r] = av.x; As[a_c + 1][a_r] = av.y;
        As[a_c + 2][a_r] = av.z; As[a_c + 3][a_r] = av.w;
        *(float4*)&Bs[b_r][b_c] = *(const float4*)&V[(size_t)(k0 + b_r) * HD_ + b_c];
        __syncthreads();
        #pragma unroll
        for (int k = 0; k < 8; k++) {
            float ar[8], br[8];
            #pragma unroll
            for (int i = 0; i < 8; i++) ar[i] = As[k][ty * 8 + i];
            #pragma unroll
            for (int j = 0; j < 8; j++) br[j] = Bs[k][tx * 8 + j];
            #pragma unroll
            for (int i = 0; i < 8; i++)
                #pragma unroll
                for (int j = 0; j < 8; j++) acc[i][j] += ar[i] * br[j];
        }
        __syncthreads();
    }

    #pragma unroll
    for (int i = 0; i < 8; i++) {
        int s = brow + ty * 8 + i;
        #pragma unroll
        for (int j = 0; j < 8; j++) {
            int d = tx * 8 + j;
            g_O[((size_t)b * S_ + s) * HID_ + h * HD_ + d] = acc[i][j];
        }
    }
}

// ------------------------------------------------------------------
// Manifold update (fused): m = O_row @ W_pinv + b_pinv  (1024 -> 8)
//                          cur_row += m @ W_attn[l] + b_attn[l]
// One block (256 thr, 8 warps) per row; warp w computes m[w].
// ------------------------------------------------------------------
__global__ void update_kernel(const float* __restrict__ W_pinv,
                              const float* __restrict__ b_pinv,
                              const float* __restrict__ Wa,
                              const float* __restrict__ ba)
{
    const int row  = blockIdx.x;
    const int tid  = threadIdx.x;
    const int warp = tid >> 5;
    const int lane = tid & 31;
    const float* orow = g_O + (size_t)row * HID_;

    __shared__ float m[MD_];
    float acc = 0.f;
    for (int i = lane; i < HID_; i += 32)
        acc += orow[i] * W_pinv[i * MD_ + warp];
    #pragma unroll
    for (int o = 16; o > 0; o >>= 1) acc += __shfl_xor_sync(0xffffffffu, acc, o);
    if (lane == 0) m[warp] = acc + b_pinv[warp];
    __syncthreads();

    float mv[MD_];
    #pragma unroll
    for (int j = 0; j < MD_; j++) mv[j] = m[j];

    #pragma unroll
    for (int t = 0; t < HID_ / 256; t++) {
        int col = tid + t * 256;
        float u = ba[col];
        #pragma unroll
        for (int j = 0; j < MD_; j++) u += mv[j] * Wa[j * HID_ + col];
        g_cur[(size_t)row * HID_ + col] += u;
    }
}

// ------------------------------------------------------------------
// Host launcher (graph-capturable: kernels only, default stream)
// ------------------------------------------------------------------
extern "C" void kernel_launch(void* const* d_in, const int* in_sizes, int n_in,
                              void* d_out, int out_size)
{
    const float* x      = (const float*)d_in[0];
    const float* W_qkv  = (const float*)d_in[1];
    const float* b_qkv  = (const float*)d_in[2];
    const float* W_pinv = (const float*)d_in[3];
    const float* b_pinv = (const float*)d_in[4];
    const float* W_attn = (const float*)d_in[5];
    const float* b_attn = (const float*)d_in[6];
    const float* W_out  = (const float*)d_in[7];
    const float* b_out  = (const float*)d_in[8];
    float* out = (float*)d_out;

    float *curp = nullptr, *qkvp = nullptr;
    cudaGetSymbolAddress((void**)&curp, g_cur);
    cudaGetSymbolAddress((void**)&qkvp, g_qkv);

    // g_cur = x
    copy_x_kernel<<<(M_ * HID_) / 4 / 256, 256>>>(x);

    for (int l = 0; l < L_; ++l) {
        // qkv = cur @ W_qkv + b_qkv
        sgemm_bias_kernel<<<dim3(3 * HID_ / 128, M_ / 128), 256>>>(
            curp, W_qkv, b_qkv, qkvp, M_, 3 * HID_, HID_);

        // split into heads, apply expmap0 to q,k
        split_expmap_kernel<<<dim3(M_, 3), 256>>>();

        // scores = Qf @ Kf^T * inv_sqrt_d   (batch 64)
        scores_kernel<<<dim3(S_ / 128, S_ / 128, BH_), 256>>>();

        // row softmax
        softmax_kernel<<<BH_ * S_, 256>>>();

        // O = P @ V, reassembled into [B,S,HID]
        pv_kernel<<<dim3(1, S_ / 128, BH_), 256>>>();

        // cur += (O @ W_pinv + b_pinv) @ W_attn[l] + b_attn[l]
        update_kernel<<<M_, 256>>>(W_pinv, b_pinv,
                                   W_attn + (size_t)l * MD_ * HID_,
                                   b_attn + (size_t)l * HID_);
    }

    // out = cur @ W_out + b_out
    sgemm_bias_kernel<<<dim3(HID_ / 128, M_ / 128), 256>>>(
        curp, W_out, b_out, out, M_, HID_, HID_);
}